// round 2
// baseline (speedup 1.0000x reference)
#include <cuda_runtime.h>

#define HDIM 128
#define TE   128
#define KC   16
#define NTHR 256

// Scratch aggregation buffer (device global: allocation-free scratch).
__device__ float g_agg[50048 * HDIM];

__device__ __forceinline__ void red_add_v4(float* addr, float a, float b, float c, float d) {
    asm volatile("red.global.add.v4.f32 [%0], {%1,%2,%3,%4};"
                 :: "l"(addr), "f"(a), "f"(b), "f"(c), "f"(d) : "memory");
}

__global__ void zero_agg_kernel(int n4) {
    int i = blockIdx.x * blockDim.x + threadIdx.x;
    if (i < n4) {
        float4 z = make_float4(0.f, 0.f, 0.f, 0.f);
        ((float4*)g_agg)[i] = z;
    }
}

// ---------------------------------------------------------------------------
// Edge pass: messages = MLP2(concat(x[row], x[col], ea)); atomic scatter into g_agg
// One block = 128 edges. 256 threads, each computes an 8x8 microtile of the
// [128 x 128] output tile. Stage-1 K=384 (gathered concat), stage-2 K=128.
// ---------------------------------------------------------------------------
__global__ void __launch_bounds__(NTHR, 2)
edge_kernel(const float* __restrict__ x, const int* __restrict__ eidx,
            const float* __restrict__ ea,
            const float* __restrict__ We1, const float* __restrict__ be1,
            const float* __restrict__ We2, const float* __restrict__ be2,
            int nE)
{
    extern __shared__ float sm[];
    float* Bs  = sm;                         // [KC][HDIM]
    float* Hsm = sm + KC * HDIM;             // [TE][HDIM+4]
    float* As  = Hsm + TE * (HDIM + 4);      // [KC][TE]
    __shared__ int rowi[TE];
    __shared__ int coli[TE];

    const int tid = threadIdx.x;
    const int tx  = tid & 15;
    const int ty  = tid >> 4;
    const int e0  = blockIdx.x * TE;

    if (tid < TE) {
        int ec = min(e0 + tid, nE - 1);
        rowi[tid] = eidx[ec];
        coli[tid] = eidx[nE + ec];
    }
    __syncthreads();

    // A-load role: thread pair per edge, 8 consecutive k each
    const int le = tid >> 1;
    const int lh = (tid & 1) * 8;
    const float* aRow = x  + (size_t)rowi[le] * HDIM;
    const float* aCol = x  + (size_t)coli[le] * HDIM;
    const float* aEa  = ea + (size_t)min(e0 + le, nE - 1) * HDIM;

    // B-load role: one (k, 8 cols) strip per thread
    const int bk = tid >> 4;
    const int bh = (tid & 15) * 8;

    float acc[8][8];
    {
        float bj[8];
        #pragma unroll
        for (int j = 0; j < 8; j++) bj[j] = be1[tx * 8 + j];
        #pragma unroll
        for (int i = 0; i < 8; i++)
            #pragma unroll
            for (int j = 0; j < 8; j++) acc[i][j] = bj[j];
    }

    // ---------------- Stage 1: [128,384] @ [384,128] + ReLU ----------------
    for (int kc = 0; kc < 24; kc++) {
        const int src = kc >> 3;            // 0:x[row] 1:x[col] 2:edge_attr
        const int k0  = (kc & 7) * KC;
        const float* abase = (src == 0) ? aRow : ((src == 1) ? aCol : aEa);
        float4 a0 = *(const float4*)(abase + k0 + lh);
        float4 a1 = *(const float4*)(abase + k0 + lh + 4);
        const float* wrow = We1 + (size_t)(kc * KC + bk) * HDIM + bh;
        float4 b0 = *(const float4*)(wrow);
        float4 b1 = *(const float4*)(wrow + 4);
        __syncthreads();
        As[(lh + 0) * TE + le] = a0.x;
        As[(lh + 1) * TE + le] = a0.y;
        As[(lh + 2) * TE + le] = a0.z;
        As[(lh + 3) * TE + le] = a0.w;
        As[(lh + 4) * TE + le] = a1.x;
        As[(lh + 5) * TE + le] = a1.y;
        As[(lh + 6) * TE + le] = a1.z;
        As[(lh + 7) * TE + le] = a1.w;
        *(float4*)&Bs[bk * HDIM + bh]     = b0;
        *(float4*)&Bs[bk * HDIM + bh + 4] = b1;
        __syncthreads();
        #pragma unroll
        for (int kk = 0; kk < KC; kk++) {
            float af[8], bf[8];
            *(float4*)&af[0] = *(const float4*)&As[kk * TE + ty * 8];
            *(float4*)&af[4] = *(const float4*)&As[kk * TE + ty * 8 + 4];
            *(float4*)&bf[0] = *(const float4*)&Bs[kk * HDIM + tx * 8];
            *(float4*)&bf[4] = *(const float4*)&Bs[kk * HDIM + tx * 8 + 4];
            #pragma unroll
            for (int i = 0; i < 8; i++)
                #pragma unroll
                for (int j = 0; j < 8; j++)
                    acc[i][j] = fmaf(af[i], bf[j], acc[i][j]);
        }
    }

    __syncthreads();
    // ReLU -> SMEM hidden tile
    #pragma unroll
    for (int i = 0; i < 8; i++) {
        const int r = ty * 8 + i;
        float* hp = &Hsm[r * (HDIM + 4) + tx * 8];
        float4 h0, h1;
        h0.x = fmaxf(acc[i][0], 0.f); h0.y = fmaxf(acc[i][1], 0.f);
        h0.z = fmaxf(acc[i][2], 0.f); h0.w = fmaxf(acc[i][3], 0.f);
        h1.x = fmaxf(acc[i][4], 0.f); h1.y = fmaxf(acc[i][5], 0.f);
        h1.z = fmaxf(acc[i][6], 0.f); h1.w = fmaxf(acc[i][7], 0.f);
        *(float4*)(hp)     = h0;
        *(float4*)(hp + 4) = h1;
    }
    {
        float bj[8];
        #pragma unroll
        for (int j = 0; j < 8; j++) bj[j] = be2[tx * 8 + j];
        #pragma unroll
        for (int i = 0; i < 8; i++)
            #pragma unroll
            for (int j = 0; j < 8; j++) acc[i][j] = bj[j];
    }
    __syncthreads();

    // ---------------- Stage 2: [128,128] @ [128,128] ----------------
    for (int kc = 0; kc < 8; kc++) {
        const float* wrow = We2 + (size_t)(kc * KC + bk) * HDIM + bh;
        float4 b0 = *(const float4*)(wrow);
        float4 b1 = *(const float4*)(wrow + 4);
        __syncthreads();
        *(float4*)&Bs[bk * HDIM + bh]     = b0;
        *(float4*)&Bs[bk * HDIM + bh + 4] = b1;
        __syncthreads();
        #pragma unroll
        for (int kk = 0; kk < KC; kk++) {
            const int k = kc * KC + kk;
            float bf[8];
            *(float4*)&bf[0] = *(const float4*)&Bs[kk * HDIM + tx * 8];
            *(float4*)&bf[4] = *(const float4*)&Bs[kk * HDIM + tx * 8 + 4];
            #pragma unroll
            for (int i = 0; i < 8; i++) {
                float a = Hsm[(ty * 8 + i) * (HDIM + 4) + k];
                #pragma unroll
                for (int j = 0; j < 8; j++)
                    acc[i][j] = fmaf(a, bf[j], acc[i][j]);
            }
        }
    }

    // Scatter-add messages into g_agg by destination (vector atomics)
    #pragma unroll
    for (int i = 0; i < 8; i++) {
        const int r = ty * 8 + i;
        if (e0 + r < nE) {
            float* dst = g_agg + (size_t)coli[r] * HDIM + tx * 8;
            red_add_v4(dst,     acc[i][0], acc[i][1], acc[i][2], acc[i][3]);
            red_add_v4(dst + 4, acc[i][4], acc[i][5], acc[i][6], acc[i][7]);
        }
    }
}

// ---------------------------------------------------------------------------
// Node pass: out = MLP2(concat(x, agg))
// ---------------------------------------------------------------------------
__global__ void __launch_bounds__(NTHR, 2)
node_kernel(const float* __restrict__ x,
            const float* __restrict__ Wn1, const float* __restrict__ bn1,
            const float* __restrict__ Wn2, const float* __restrict__ bn2,
            float* __restrict__ out, int nN)
{
    extern __shared__ float sm[];
    float* Bs  = sm;
    float* Hsm = sm + KC * HDIM;
    float* As  = Hsm + TE * (HDIM + 4);

    const int tid = threadIdx.x;
    const int tx  = tid & 15;
    const int ty  = tid >> 4;
    const int n0  = blockIdx.x * TE;

    const int le = tid >> 1;
    const int lh = (tid & 1) * 8;
    const size_t nrow = (size_t)min(n0 + le, nN - 1) * HDIM;
    const float* aX = x + nrow;
    const float* aG = g_agg + nrow;

    const int bk = tid >> 4;
    const int bh = (tid & 15) * 8;

    float acc[8][8];
    {
        float bj[8];
        #pragma unroll
        for (int j = 0; j < 8; j++) bj[j] = bn1[tx * 8 + j];
        #pragma unroll
        for (int i = 0; i < 8; i++)
            #pragma unroll
            for (int j = 0; j < 8; j++) acc[i][j] = bj[j];
    }

    // Stage 1: K = 256 (x ++ agg)
    for (int kc = 0; kc < 16; kc++) {
        const int k0 = (kc & 7) * KC;
        const float* abase = (kc < 8) ? aX : aG;
        float4 a0 = *(const float4*)(abase + k0 + lh);
        float4 a1 = *(const float4*)(abase + k0 + lh + 4);
        const float* wrow = Wn1 + (size_t)(kc * KC + bk) * HDIM + bh;
        float4 b0 = *(const float4*)(wrow);
        float4 b1 = *(const float4*)(wrow + 4);
        __syncthreads();
        As[(lh + 0) * TE + le] = a0.x;
        As[(lh + 1) * TE + le] = a0.y;
        As[(lh + 2) * TE + le] = a0.z;
        As[(lh + 3) * TE + le] = a0.w;
        As[(lh + 4) * TE + le] = a1.x;
        As[(lh + 5) * TE + le] = a1.y;
        As[(lh + 6) * TE + le] = a1.z;
        As[(lh + 7) * TE + le] = a1.w;
        *(float4*)&Bs[bk * HDIM + bh]     = b0;
        *(float4*)&Bs[bk * HDIM + bh + 4] = b1;
        __syncthreads();
        #pragma unroll
        for (int kk = 0; kk < KC; kk++) {
            float af[8], bf[8];
            *(float4*)&af[0] = *(const float4*)&As[kk * TE + ty * 8];
            *(float4*)&af[4] = *(const float4*)&As[kk * TE + ty * 8 + 4];
            *(float4*)&bf[0] = *(const float4*)&Bs[kk * HDIM + tx * 8];
            *(float4*)&bf[4] = *(const float4*)&Bs[kk * HDIM + tx * 8 + 4];
            #pragma unroll
            for (int i = 0; i < 8; i++)
                #pragma unroll
                for (int j = 0; j < 8; j++)
                    acc[i][j] = fmaf(af[i], bf[j], acc[i][j]);
        }
    }

    __syncthreads();
    #pragma unroll
    for (int i = 0; i < 8; i++) {
        const int r = ty * 8 + i;
        float* hp = &Hsm[r * (HDIM + 4) + tx * 8];
        float4 h0, h1;
        h0.x = fmaxf(acc[i][0], 0.f); h0.y = fmaxf(acc[i][1], 0.f);
        h0.z = fmaxf(acc[i][2], 0.f); h0.w = fmaxf(acc[i][3], 0.f);
        h1.x = fmaxf(acc[i][4], 0.f); h1.y = fmaxf(acc[i][5], 0.f);
        h1.z = fmaxf(acc[i][6], 0.f); h1.w = fmaxf(acc[i][7], 0.f);
        *(float4*)(hp)     = h0;
        *(float4*)(hp + 4) = h1;
    }
    {
        float bj[8];
        #pragma unroll
        for (int j = 0; j < 8; j++) bj[j] = bn2[tx * 8 + j];
        #pragma unroll
        for (int i = 0; i < 8; i++)
            #pragma unroll
            for (int j = 0; j < 8; j++) acc[i][j] = bj[j];
    }
    __syncthreads();

    // Stage 2: K = 128
    for (int kc = 0; kc < 8; kc++) {
        const float* wrow = Wn2 + (size_t)(kc * KC + bk) * HDIM + bh;
        float4 b0 = *(const float4*)(wrow);
        float4 b1 = *(const float4*)(wrow + 4);
        __syncthreads();
        *(float4*)&Bs[bk * HDIM + bh]     = b0;
        *(float4*)&Bs[bk * HDIM + bh + 4] = b1;
        __syncthreads();
        #pragma unroll
        for (int kk = 0; kk < KC; kk++) {
            const int k = kc * KC + kk;
            float bf[8];
            *(float4*)&bf[0] = *(const float4*)&Bs[kk * HDIM + tx * 8];
            *(float4*)&bf[4] = *(const float4*)&Bs[kk * HDIM + tx * 8 + 4];
            #pragma unroll
            for (int i = 0; i < 8; i++) {
                float a = Hsm[(ty * 8 + i) * (HDIM + 4) + k];
                #pragma unroll
                for (int j = 0; j < 8; j++)
                    acc[i][j] = fmaf(a, bf[j], acc[i][j]);
            }
        }
    }

    #pragma unroll
    for (int i = 0; i < 8; i++) {
        const int r = ty * 8 + i;
        if (n0 + r < nN) {
            float* dst = out + (size_t)(n0 + r) * HDIM + tx * 8;
            float4 o0 = make_float4(acc[i][0], acc[i][1], acc[i][2], acc[i][3]);
            float4 o1 = make_float4(acc[i][4], acc[i][5], acc[i][6], acc[i][7]);
            *(float4*)(dst)     = o0;
            *(float4*)(dst + 4) = o1;
        }
    }
}

extern "C" void kernel_launch(void* const* d_in, const int* in_sizes, int n_in,
                              void* d_out, int out_size)
{
    const float* x    = (const float*)d_in[0];
    const int*   eidx = (const int*)d_in[1];     // int32! harness has no int64 path
    const float* ea   = (const float*)d_in[2];
    const float* We1  = (const float*)d_in[3];
    const float* be1  = (const float*)d_in[4];
    const float* We2  = (const float*)d_in[5];
    const float* be2  = (const float*)d_in[6];
    const float* Wn1  = (const float*)d_in[7];
    const float* bn1  = (const float*)d_in[8];
    const float* Wn2  = (const float*)d_in[9];
    const float* bn2  = (const float*)d_in[10];
    float* out = (float*)d_out;

    const int nN = in_sizes[0] / HDIM;
    const int nE = in_sizes[1] / 2;

    const int smem_bytes = (KC * HDIM + TE * (HDIM + 4) + KC * TE) * (int)sizeof(float);
    cudaFuncSetAttribute(edge_kernel, cudaFuncAttributeMaxDynamicSharedMemorySize, smem_bytes);
    cudaFuncSetAttribute(node_kernel, cudaFuncAttributeMaxDynamicSharedMemorySize, smem_bytes);

    const int n4 = nN * HDIM / 4;
    zero_agg_kernel<<<(n4 + 255) / 256, 256>>>(n4);
    edge_kernel<<<(nE + TE - 1) / TE, NTHR, smem_bytes>>>(x, eidx, ea, We1, be1, We2, be2, nE);
    node_kernel<<<(nN + TE - 1) / TE, NTHR, smem_bytes>>>(x, Wn1, bn1, Wn2, bn2, out, nN);
}

// round 8
// speedup vs baseline: 1.6381x; 1.6381x over previous
#include <cuda_runtime.h>
#include <cuda.h>
#include <cstdint>

#define H    128
#define TM   128
#define KC   16
#define NTHR 256

// ---------------- device scratch (allocation-free) ----------------
__device__ float g_agg[50048 * H];
__device__ float g_P[50048 * H];    // x @ We1[0:128]    (row-part)
__device__ float g_Q[50048 * H];    // x @ We1[128:256]  (col-part)

__device__ __forceinline__ void red_add_v4(float* addr, float a, float b, float c, float d) {
    asm volatile("red.global.add.v4.f32 [%0], {%1,%2,%3,%4};"
                 :: "l"(addr), "f"(a), "f"(b), "f"(c), "f"(d) : "memory");
}

__global__ void zero_agg_kernel(int n4) {
    int i = blockIdx.x * blockDim.x + threadIdx.x;
    if (i < n4) ((float4*)g_agg)[i] = make_float4(0.f, 0.f, 0.f, 0.f);
}

// ---------------------------------------------------------------------------
// prep_pq: P = x @ We1[0:128,:],  Q = x @ We1[128:256,:]
// grid.y = 0 -> P, 1 -> Q. One block = 128 node rows, K = 128.
// ---------------------------------------------------------------------------
__global__ void __launch_bounds__(NTHR, 2)
prep_pq_kernel(const float* __restrict__ x, const float* __restrict__ We1, int nN)
{
    extern __shared__ float sm[];
    float* Bs = sm;                 // [KC][H]
    float* As = sm + KC * H;        // [KC][TM]

    const int tid = threadIdx.x;
    const int tx  = tid & 15;
    const int ty  = tid >> 4;
    const int n0  = blockIdx.x * TM;

    const float* W = We1 + (size_t)(blockIdx.y * H) * H;   // rows [128*y, 128*y+128)
    float* outbuf  = blockIdx.y ? g_Q : g_P;

    const int le = tid >> 1;
    const int lh = (tid & 1) * 8;
    const float* aX = x + (size_t)min(n0 + le, nN - 1) * H;

    const int bk = tid >> 4;
    const int bh = (tid & 15) * 8;

    float acc[8][8];
    #pragma unroll
    for (int i = 0; i < 8; i++)
        #pragma unroll
        for (int j = 0; j < 8; j++) acc[i][j] = 0.f;

    for (int kc = 0; kc < 8; kc++) {
        const int k0 = kc * KC;
        float4 a0 = *(const float4*)(aX + k0 + lh);
        float4 a1 = *(const float4*)(aX + k0 + lh + 4);
        const float* wrow = W + (size_t)(k0 + bk) * H + bh;
        float4 b0 = *(const float4*)(wrow);
        float4 b1 = *(const float4*)(wrow + 4);
        __syncthreads();
        As[(lh + 0) * TM + le] = a0.x; As[(lh + 1) * TM + le] = a0.y;
        As[(lh + 2) * TM + le] = a0.z; As[(lh + 3) * TM + le] = a0.w;
        As[(lh + 4) * TM + le] = a1.x; As[(lh + 5) * TM + le] = a1.y;
        As[(lh + 6) * TM + le] = a1.z; As[(lh + 7) * TM + le] = a1.w;
        *(float4*)&Bs[bk * H + bh]     = b0;
        *(float4*)&Bs[bk * H + bh + 4] = b1;
        __syncthreads();
        #pragma unroll
        for (int kk = 0; kk < KC; kk++) {
            float af[8], bf[8];
            *(float4*)&af[0] = *(const float4*)&As[kk * TM + ty * 8];
            *(float4*)&af[4] = *(const float4*)&As[kk * TM + ty * 8 + 4];
            *(float4*)&bf[0] = *(const float4*)&Bs[kk * H + tx * 8];
            *(float4*)&bf[4] = *(const float4*)&Bs[kk * H + tx * 8 + 4];
            #pragma unroll
            for (int i = 0; i < 8; i++)
                #pragma unroll
                for (int j = 0; j < 8; j++)
                    acc[i][j] = fmaf(af[i], bf[j], acc[i][j]);
        }
    }

    #pragma unroll
    for (int i = 0; i < 8; i++) {
        const int r = ty * 8 + i;
        if (n0 + r < nN) {
            float* dst = outbuf + (size_t)(n0 + r) * H + tx * 8;
            *(float4*)(dst)     = make_float4(acc[i][0], acc[i][1], acc[i][2], acc[i][3]);
            *(float4*)(dst + 4) = make_float4(acc[i][4], acc[i][5], acc[i][6], acc[i][7]);
        }
    }
}

// ---------------------------------------------------------------------------
// Edge pass:
//   hidden = relu( ea @ We1_c + P[row] + Q[col] + b1 )   (GEMM K=128 + gather-add)
//   msg    = hidden @ We2 + b2                           (GEMM K=128)
//   scatter-add msg into g_agg[col]
// ---------------------------------------------------------------------------
__global__ void __launch_bounds__(NTHR, 2)
edge_kernel(const float* __restrict__ ea, const int* __restrict__ eidx,
            const float* __restrict__ We1, const float* __restrict__ be1,
            const float* __restrict__ We2, const float* __restrict__ be2,
            int nE)
{
    extern __shared__ float sm[];
    float* Bs  = sm;                       // [KC][H]
    float* Hsm = sm + KC * H;              // [TM][H+4]
    float* As  = Hsm + TM * (H + 4);       // [KC][TM]
    __shared__ int rowi[TM];
    __shared__ int coli[TM];

    const int tid = threadIdx.x;
    const int tx  = tid & 15;
    const int ty  = tid >> 4;
    const int e0  = blockIdx.x * TM;

    if (tid < TM) {
        int ec = min(e0 + tid, nE - 1);
        rowi[tid] = eidx[ec];
        coli[tid] = eidx[nE + ec];
    }
    __syncthreads();

    const int le = tid >> 1;
    const int lh = (tid & 1) * 8;
    const float* aEa = ea + (size_t)min(e0 + le, nE - 1) * H;

    const int bk = tid >> 4;
    const int bh = (tid & 15) * 8;

    const float* We1c = We1 + (size_t)256 * H;   // rows 256..383: edge_attr part

    float acc[8][8];
    {
        float bj[8];
        #pragma unroll
        for (int j = 0; j < 8; j++) bj[j] = be1[tx * 8 + j];
        #pragma unroll
        for (int i = 0; i < 8; i++)
            #pragma unroll
            for (int j = 0; j < 8; j++) acc[i][j] = bj[j];
    }

    // ---------------- Stage 1: ea @ We1_c  (K=128) ----------------
    for (int kc = 0; kc < 8; kc++) {
        const int k0 = kc * KC;
        float4 a0 = *(const float4*)(aEa + k0 + lh);
        float4 a1 = *(const float4*)(aEa + k0 + lh + 4);
        const float* wrow = We1c + (size_t)(k0 + bk) * H + bh;
        float4 b0 = *(const float4*)(wrow);
        float4 b1 = *(const float4*)(wrow + 4);
        __syncthreads();
        As[(lh + 0) * TM + le] = a0.x; As[(lh + 1) * TM + le] = a0.y;
        As[(lh + 2) * TM + le] = a0.z; As[(lh + 3) * TM + le] = a0.w;
        As[(lh + 4) * TM + le] = a1.x; As[(lh + 5) * TM + le] = a1.y;
        As[(lh + 6) * TM + le] = a1.z; As[(lh + 7) * TM + le] = a1.w;
        *(float4*)&Bs[bk * H + bh]     = b0;
        *(float4*)&Bs[bk * H + bh + 4] = b1;
        __syncthreads();
        #pragma unroll
        for (int kk = 0; kk < KC; kk++) {
            float af[8], bf[8];
            *(float4*)&af[0] = *(const float4*)&As[kk * TM + ty * 8];
            *(float4*)&af[4] = *(const float4*)&As[kk * TM + ty * 8 + 4];
            *(float4*)&bf[0] = *(const float4*)&Bs[kk * H + tx * 8];
            *(float4*)&bf[4] = *(const float4*)&Bs[kk * H + tx * 8 + 4];
            #pragma unroll
            for (int i = 0; i < 8; i++)
                #pragma unroll
                for (int j = 0; j < 8; j++)
                    acc[i][j] = fmaf(af[i], bf[j], acc[i][j]);
        }
    }

    // ---------------- gather-add P[row] + Q[col], ReLU -> Hsm ----------------
    __syncthreads();
    #pragma unroll
    for (int i = 0; i < 8; i++) {
        const int r = ty * 8 + i;
        const float* pp = g_P + (size_t)rowi[r] * H + tx * 8;
        const float* qq = g_Q + (size_t)coli[r] * H + tx * 8;
        float4 p0 = *(const float4*)(pp);
        float4 p1 = *(const float4*)(pp + 4);
        float4 q0 = *(const float4*)(qq);
        float4 q1 = *(const float4*)(qq + 4);
        float* hp = &Hsm[r * (H + 4) + tx * 8];
        float4 h0, h1;
        h0.x = fmaxf(acc[i][0] + p0.x + q0.x, 0.f);
        h0.y = fmaxf(acc[i][1] + p0.y + q0.y, 0.f);
        h0.z = fmaxf(acc[i][2] + p0.z + q0.z, 0.f);
        h0.w = fmaxf(acc[i][3] + p0.w + q0.w, 0.f);
        h1.x = fmaxf(acc[i][4] + p1.x + q1.x, 0.f);
        h1.y = fmaxf(acc[i][5] + p1.y + q1.y, 0.f);
        h1.z = fmaxf(acc[i][6] + p1.z + q1.z, 0.f);
        h1.w = fmaxf(acc[i][7] + p1.w + q1.w, 0.f);
        *(float4*)(hp)     = h0;
        *(float4*)(hp + 4) = h1;
    }
    {
        float bj[8];
        #pragma unroll
        for (int j = 0; j < 8; j++) bj[j] = be2[tx * 8 + j];
        #pragma unroll
        for (int i = 0; i < 8; i++)
            #pragma unroll
            for (int j = 0; j < 8; j++) acc[i][j] = bj[j];
    }
    __syncthreads();

    // ---------------- Stage 2: hidden @ We2  (K=128) ----------------
    for (int kc = 0; kc < 8; kc++) {
        const float* wrow = We2 + (size_t)(kc * KC + bk) * H + bh;
        float4 b0 = *(const float4*)(wrow);
        float4 b1 = *(const float4*)(wrow + 4);
        __syncthreads();
        *(float4*)&Bs[bk * H + bh]     = b0;
        *(float4*)&Bs[bk * H + bh + 4] = b1;
        __syncthreads();
        #pragma unroll
        for (int kk = 0; kk < KC; kk++) {
            const int k = kc * KC + kk;
            float bf[8];
            *(float4*)&bf[0] = *(const float4*)&Bs[kk * H + tx * 8];
            *(float4*)&bf[4] = *(const float4*)&Bs[kk * H + tx * 8 + 4];
            #pragma unroll
            for (int i = 0; i < 8; i++) {
                float a = Hsm[(ty * 8 + i) * (H + 4) + k];
                #pragma unroll
                for (int j = 0; j < 8; j++)
                    acc[i][j] = fmaf(a, bf[j], acc[i][j]);
            }
        }
    }

    // ---------------- scatter-add ----------------
    #pragma unroll
    for (int i = 0; i < 8; i++) {
        const int r = ty * 8 + i;
        if (e0 + r < nE) {
            float* dst = g_agg + (size_t)coli[r] * H + tx * 8;
            red_add_v4(dst,     acc[i][0], acc[i][1], acc[i][2], acc[i][3]);
            red_add_v4(dst + 4, acc[i][4], acc[i][5], acc[i][6], acc[i][7]);
        }
    }
}

// ---------------------------------------------------------------------------
// Node pass: out = MLP2(concat(x, agg))
// ---------------------------------------------------------------------------
__global__ void __launch_bounds__(NTHR, 2)
node_kernel(const float* __restrict__ x,
            const float* __restrict__ Wn1, const float* __restrict__ bn1,
            const float* __restrict__ Wn2, const float* __restrict__ bn2,
            float* __restrict__ out, int nN)
{
    extern __shared__ float sm[];
    float* Bs  = sm;
    float* Hsm = sm + KC * H;
    float* As  = Hsm + TM * (H + 4);

    const int tid = threadIdx.x;
    const int tx  = tid & 15;
    const int ty  = tid >> 4;
    const int n0  = blockIdx.x * TM;

    const int le = tid >> 1;
    const int lh = (tid & 1) * 8;
    const size_t nrow = (size_t)min(n0 + le, nN - 1) * H;
    const float* aX = x + nrow;
    const float* aG = g_agg + nrow;

    const int bk = tid >> 4;
    const int bh = (tid & 15) * 8;

    float acc[8][8];
    {
        float bj[8];
        #pragma unroll
        for (int j = 0; j < 8; j++) bj[j] = bn1[tx * 8 + j];
        #pragma unroll
        for (int i = 0; i < 8; i++)
            #pragma unroll
            for (int j = 0; j < 8; j++) acc[i][j] = bj[j];
    }

    for (int kc = 0; kc < 16; kc++) {
        const int k0 = (kc & 7) * KC;
        const float* abase = (kc < 8) ? aX : aG;
        float4 a0 = *(const float4*)(abase + k0 + lh);
        float4 a1 = *(const float4*)(abase + k0 + lh + 4);
        const float* wrow = Wn1 + (size_t)(kc * KC + bk) * H + bh;
        float4 b0 = *(const float4*)(wrow);
        float4 b1 = *(const float4*)(wrow + 4);
        __syncthreads();
        As[(lh + 0) * TM + le] = a0.x; As[(lh + 1) * TM + le] = a0.y;
        As[(lh + 2) * TM + le] = a0.z; As[(lh + 3) * TM + le] = a0.w;
        As[(lh + 4) * TM + le] = a1.x; As[(lh + 5) * TM + le] = a1.y;
        As[(lh + 6) * TM + le] = a1.z; As[(lh + 7) * TM + le] = a1.w;
        *(float4*)&Bs[bk * H + bh]     = b0;
        *(float4*)&Bs[bk * H + bh + 4] = b1;
        __syncthreads();
        #pragma unroll
        for (int kk = 0; kk < KC; kk++) {
            float af[8], bf[8];
            *(float4*)&af[0] = *(const float4*)&As[kk * TM + ty * 8];
            *(float4*)&af[4] = *(const float4*)&As[kk * TM + ty * 8 + 4];
            *(float4*)&bf[0] = *(const float4*)&Bs[kk * H + tx * 8];
            *(float4*)&bf[4] = *(const float4*)&Bs[kk * H + tx * 8 + 4];
            #pragma unroll
            for (int i = 0; i < 8; i++)
                #pragma unroll
                for (int j = 0; j < 8; j++)
                    acc[i][j] = fmaf(af[i], bf[j], acc[i][j]);
        }
    }

    __syncthreads();
    #pragma unroll
    for (int i = 0; i < 8; i++) {
        const int r = ty * 8 + i;
        float* hp = &Hsm[r * (H + 4) + tx * 8];
        float4 h0, h1;
        h0.x = fmaxf(acc[i][0], 0.f); h0.y = fmaxf(acc[i][1], 0.f);
        h0.z = fmaxf(acc[i][2], 0.f); h0.w = fmaxf(acc[i][3], 0.f);
        h1.x = fmaxf(acc[i][4], 0.f); h1.y = fmaxf(acc[i][5], 0.f);
        h1.z = fmaxf(acc[i][6], 0.f); h1.w = fmaxf(acc[i][7], 0.f);
        *(float4*)(hp)     = h0;
        *(float4*)(hp + 4) = h1;
    }
    {
        float bj[8];
        #pragma unroll
        for (int j = 0; j < 8; j++) bj[j] = bn2[tx * 8 + j];
        #pragma unroll
        for (int i = 0; i < 8; i++)
            #pragma unroll
            for (int j = 0; j < 8; j++) acc[i][j] = bj[j];
    }
    __syncthreads();

    for (int kc = 0; kc < 8; kc++) {
        const float* wrow = Wn2 + (size_t)(kc * KC + bk) * H + bh;
        float4 b0 = *(const float4*)(wrow);
        float4 b1 = *(const float4*)(wrow + 4);
        __syncthreads();
        *(float4*)&Bs[bk * H + bh]     = b0;
        *(float4*)&Bs[bk * H + bh + 4] = b1;
        __syncthreads();
        #pragma unroll
        for (int kk = 0; kk < KC; kk++) {
            const int k = kc * KC + kk;
            float bf[8];
            *(float4*)&bf[0] = *(const float4*)&Bs[kk * H + tx * 8];
            *(float4*)&bf[4] = *(const float4*)&Bs[kk * H + tx * 8 + 4];
            #pragma unroll
            for (int i = 0; i < 8; i++) {
                float a = Hsm[(ty * 8 + i) * (H + 4) + k];
                #pragma unroll
                for (int j = 0; j < 8; j++)
                    acc[i][j] = fmaf(a, bf[j], acc[i][j]);
            }
        }
    }

    #pragma unroll
    for (int i = 0; i < 8; i++) {
        const int r = ty * 8 + i;
        if (n0 + r < nN) {
            float* dst = out + (size_t)(n0 + r) * H + tx * 8;
            *(float4*)(dst)     = make_float4(acc[i][0], acc[i][1], acc[i][2], acc[i][3]);
            *(float4*)(dst + 4) = make_float4(acc[i][4], acc[i][5], acc[i][6], acc[i][7]);
        }
    }
}

extern "C" void kernel_launch(void* const* d_in, const int* in_sizes, int n_in,
                              void* d_out, int out_size)
{
    const float* x    = (const float*)d_in[0];
    const int*   eidx = (const int*)d_in[1];
    const float* ea   = (const float*)d_in[2];
    const float* We1  = (const float*)d_in[3];
    const float* be1  = (const float*)d_in[4];
    const float* We2  = (const float*)d_in[5];
    const float* be2  = (const float*)d_in[6];
    const float* Wn1  = (const float*)d_in[7];
    const float* bn1  = (const float*)d_in[8];
    const float* Wn2  = (const float*)d_in[9];
    const float* bn2  = (const float*)d_in[10];
    float* out = (float*)d_out;

    const int nN = in_sizes[0] / H;
    const int nE = in_sizes[1] / 2;

    const int big_smem  = (KC * H + TM * (H + 4) + KC * TM) * (int)sizeof(float);
    const int prep_smem = (KC * H + KC * TM) * (int)sizeof(float);
    cudaFuncSetAttribute(edge_kernel, cudaFuncAttributeMaxDynamicSharedMemorySize, big_smem);
    cudaFuncSetAttribute(node_kernel, cudaFuncAttributeMaxDynamicSharedMemorySize, big_smem);
    cudaFuncSetAttribute(prep_pq_kernel, cudaFuncAttributeMaxDynamicSharedMemorySize, prep_smem);

    const int n4 = nN * H / 4;
    zero_agg_kernel<<<(n4 + 255) / 256, 256>>>(n4);

    dim3 pq_grid((nN + TM - 1) / TM, 2);
    prep_pq_kernel<<<pq_grid, NTHR, prep_smem>>>(x, We1, nN);

    edge_kernel<<<(nE + TM - 1) / TM, NTHR, big_smem>>>(ea, eidx, We1, be1, We2, be2, nE);
    node_kernel<<<(nN + TM - 1) / TM, NTHR, big_smem>>>(x, Wn1, bn1, Wn2, bn2, out, nN);
}